// round 7
// baseline (speedup 1.0000x reference)
#include <cuda_runtime.h>
#include <cuda_bf16.h>
#include <cstdint>

// Problem dims (fixed)
#define T_SEQ 2048
#define E_DIM 1024
#define N_HEADS 16
#define D_HEAD 64
#define NB 10
#define ML 2048
#define NQKVR 3232          // 1024*3 + 160
#define WT_ROWS 4256        // 3232 (QKVR) + 1024 (proj)

// ---------------------------------------------------------------------------
// Scratch (device globals; no runtime allocation allowed)
// ---------------------------------------------------------------------------
__device__ __nv_bfloat16 g_Xh[T_SEQ * E_DIM];
__device__ __nv_bfloat16 g_Xl[T_SEQ * E_DIM];
__device__ __nv_bfloat16 g_WTh[WT_ROWS * E_DIM];
__device__ __nv_bfloat16 g_WTl[WT_ROWS * E_DIM];
__device__ __nv_bfloat16 g_Ph[T_SEQ * 3072];   // QKV hi (Q pre-scaled)
__device__ __nv_bfloat16 g_Pl[T_SEQ * 3072];   // QKV lo
__device__ __nv_bfloat16 g_AOh[T_SEQ * E_DIM];
__device__ __nv_bfloat16 g_AOl[T_SEQ * E_DIM];
__device__ float g_QKVR[T_SEQ * NQKVR];        // only R cols (3072..) used

// ---------------------------------------------------------------------------
// PTX helpers (sm_80-baseline ISA only: mma.sync / ldmatrix / cp.async)
// ---------------------------------------------------------------------------
__device__ __forceinline__ uint32_t smem_u32(const void* p) {
    uint32_t a;
    asm("{ .reg .u64 t; cvta.to.shared.u64 t, %1; cvt.u32.u64 %0, t; }"
        : "=r"(a) : "l"(p));
    return a;
}

#define LDSM_X4(r, a)                                                         \
    asm volatile("ldmatrix.sync.aligned.m8n8.x4.shared.b16 {%0,%1,%2,%3}, [%4];" \
                 : "=r"((r)[0]), "=r"((r)[1]), "=r"((r)[2]), "=r"((r)[3])     \
                 : "r"(a))
#define LDSM_X4T(r, a)                                                        \
    asm volatile("ldmatrix.sync.aligned.m8n8.x4.trans.shared.b16 {%0,%1,%2,%3}, [%4];" \
                 : "=r"((r)[0]), "=r"((r)[1]), "=r"((r)[2]), "=r"((r)[3])     \
                 : "r"(a))
#define LDSM_X2(r, a)                                                         \
    asm volatile("ldmatrix.sync.aligned.m8n8.x2.shared.b16 {%0,%1}, [%2];"    \
                 : "=r"((r)[0]), "=r"((r)[1]) : "r"(a))
#define MMA16816(d, a, b)                                                     \
    asm volatile("mma.sync.aligned.m16n8k16.row.col.f32.bf16.bf16.f32 "       \
                 "{%0,%1,%2,%3},{%4,%5,%6,%7},{%8,%9},{%0,%1,%2,%3};"         \
                 : "+f"((d)[0]), "+f"((d)[1]), "+f"((d)[2]), "+f"((d)[3])     \
                 : "r"((a)[0]), "r"((a)[1]), "r"((a)[2]), "r"((a)[3]),        \
                   "r"((b)[0]), "r"((b)[1]))
#define CP_ASYNC16(dst, src)                                                  \
    asm volatile("cp.async.cg.shared.global [%0], [%1], 16;"                  \
                 :: "r"(dst), "l"(src))
#define CP_COMMIT asm volatile("cp.async.commit_group;" ::: "memory")
#define CP_WAIT(n) asm volatile("cp.async.wait_group %0;" :: "n"(n) : "memory")

__device__ __forceinline__ uint32_t pk2(float a, float b) {
    __nv_bfloat162 t = __floats2bfloat162_rn(a, b);
    return *reinterpret_cast<uint32_t*>(&t);
}
__device__ __forceinline__ float bfr(float x) {
    return __bfloat162float(__float2bfloat16(x));
}

// ---------------------------------------------------------------------------
// Vectorized fp32 -> bf16 hi/lo split
// ---------------------------------------------------------------------------
__global__ void fsplit_kernel(const float* __restrict__ s,
                              __nv_bfloat16* __restrict__ dh,
                              __nv_bfloat16* __restrict__ dl, int n4) {
    int i = blockIdx.x * blockDim.x + threadIdx.x;
    if (i < n4) {
        float4 x = reinterpret_cast<const float4*>(s)[i];
        float h0 = bfr(x.x), h1 = bfr(x.y), h2 = bfr(x.z), h3 = bfr(x.w);
        reinterpret_cast<uint2*>(dh)[i] = make_uint2(pk2(h0, h1), pk2(h2, h3));
        reinterpret_cast<uint2*>(dl)[i] =
            make_uint2(pk2(x.x - h0, x.y - h1), pk2(x.z - h2, x.w - h3));
    }
}

// ---------------------------------------------------------------------------
// Transpose+split: all 5 weights in ONE launch (z selects weight)
// z: 0=W_q(row 0), 1=W_k(1024), 2=W_v(2048), 3=W_proj(3232), 4=W_r(3072,N=160)
// ---------------------------------------------------------------------------
struct TS5 { const float* w0; const float* w1; const float* w2;
             const float* w3; const float* w4; };

__global__ void tsplit5_kernel(TS5 p,
                               __nv_bfloat16* __restrict__ dh,
                               __nv_bfloat16* __restrict__ dl) {
    __shared__ float t[32][33];
    const int z = blockIdx.z;
    const int N = (z == 4) ? 160 : 1024;
    const int n0 = blockIdx.x * 32, k0 = blockIdx.y * 32;
    if (n0 >= N) return;
    const float* W = (&p.w0)[z];
    const int rowoff = (z == 0) ? 0 : (z == 1) ? 1024 : (z == 2) ? 2048
                     : (z == 3) ? 3232 : 3072;
    const int tx = threadIdx.x, ty = threadIdx.y;  // 32 x 8
#pragma unroll
    for (int r = 0; r < 4; r++)
        t[ty + 8 * r][tx] = W[(size_t)(k0 + ty + 8 * r) * N + n0 + tx];
    __syncthreads();
    const int tid = ty * 32 + tx;
#pragma unroll
    for (int rr = 0; rr < 2; rr++) {
        int row = (tid >> 4) + 16 * rr;   // local n
        int c = tid & 15;                 // k pair
        float x0 = t[2 * c][row], x1 = t[2 * c + 1][row];
        float h0 = bfr(x0), h1 = bfr(x1);
        size_t o = (size_t)(rowoff + n0 + row) * E_DIM + k0 + 2 * c;
        *reinterpret_cast<uint32_t*>(dh + o) = pk2(h0, h1);
        *reinterpret_cast<uint32_t*>(dl + o) = pk2(x0 - h0, x1 - h1);
    }
}

// ---------------------------------------------------------------------------
// mma.sync GEMM: C[2048, N] = A[2048,1024] @ BT[N,1024]^T (+ inline bias)
// 3-term bf16 split. CTA tile 128 x BN, BK=32, 8 warps, 3-stage cp.async.
// MODE 0: fp32 to C with bias bq[col].
// MODE 1: cols<3072 -> bf16 hi/lo (Q cols +b_q then *0.125; K/V bias 0);
//         cols>=3072 -> fp32 to C with bias br[col-3072].
// SMEM rows are 64B (32 bf16); swizzle: chunk c(0..3) ^= (row>>1)&3.
// ---------------------------------------------------------------------------
template <int MODE, int BN>
__global__ __launch_bounds__(256, 2) void gemm_mma3(
    const __nv_bfloat16* __restrict__ Ah, const __nv_bfloat16* __restrict__ Al,
    const __nv_bfloat16* __restrict__ Bh, const __nv_bfloat16* __restrict__ Bl,
    const float* __restrict__ bq, const float* __restrict__ br,
    float* __restrict__ C,
    __nv_bfloat16* __restrict__ Oh, __nv_bfloat16* __restrict__ Ol,
    int N, int ldc)
{
    constexpr int ASZ = 8192;          // 128 rows x 64B
    constexpr int BSZ = BN * 64;       // BN rows x 64B
    constexpr int STAGE = 2 * ASZ + 2 * BSZ;
    constexpr int NT = BN / 32;        // nt count per warp

    extern __shared__ char smraw[];
    const uint32_t sb = smem_u32(smraw);
    const int tid = threadIdx.x, wid = tid >> 5, lane = tid & 31;
    const int m0 = blockIdx.y * 128, n0 = blockIdx.x * BN;
    const int ntile = min(BN, N - n0);

    const int wm = (wid & 1) * 64;
    const int wn = (wid >> 1) * (BN / 4);

    const __nv_bfloat16* baseA_h = Ah + (size_t)m0 * E_DIM;
    const __nv_bfloat16* baseA_l = Al + (size_t)m0 * E_DIM;
    const __nv_bfloat16* baseB_h = Bh + (size_t)n0 * E_DIM;
    const __nv_bfloat16* baseB_l = Bl + (size_t)n0 * E_DIM;

    auto load_tile = [&](int kt, int buf) {
        const uint32_t base = sb + buf * STAGE;
        // A hi/lo: 128 rows x 4 chunks each
#pragma unroll
        for (int half = 0; half < 2; half++) {
            const __nv_bfloat16* s = (half ? baseA_l : baseA_h) + kt * 32;
            const uint32_t dsta = base + half * ASZ;
#pragma unroll
            for (int i = 0; i < 2; i++) {
                int idx = tid + i * 256;
                int row = idx >> 2, c = idx & 3;
                uint32_t dst = dsta +
                    (uint32_t)(row * 64 + ((c ^ ((row >> 1) & 3)) << 4));
                CP_ASYNC16(dst, s + (size_t)row * E_DIM + c * 8);
            }
        }
        // B hi/lo: BN rows x 4 chunks each
#pragma unroll
        for (int half = 0; half < 2; half++) {
            const __nv_bfloat16* s = (half ? baseB_l : baseB_h) + kt * 32;
            const uint32_t dstb = base + 2 * ASZ + half * BSZ;
#pragma unroll
            for (int i = 0; i < BN * 4 / 256; i++) {
                int idx = tid + i * 256;
                int row = idx >> 2, c = idx & 3;
                uint32_t dst = dstb +
                    (uint32_t)(row * 64 + ((c ^ ((row >> 1) & 3)) << 4));
                CP_ASYNC16(dst, s + (size_t)row * E_DIM + c * 8);
            }
        }
    };

    float acc[4][NT][4];
#pragma unroll
    for (int mt = 0; mt < 4; mt++)
#pragma unroll
        for (int nt = 0; nt < NT; nt++)
#pragma unroll
            for (int r = 0; r < 4; r++) acc[mt][nt][r] = 0.f;

    const int lr = lane & 7;
    const int ls = lane >> 3;

    load_tile(0, 0); CP_COMMIT;
    load_tile(1, 1); CP_COMMIT;

    for (int kt = 0; kt < 32; kt++) {
        if (kt < 30) {
            load_tile(kt + 2, (kt + 2) % 3);
            CP_COMMIT;
            CP_WAIT(2);
        } else if (kt == 30) {
            CP_WAIT(1);
        } else {
            CP_WAIT(0);
        }
        __syncthreads();

        const uint32_t cb = sb + (kt % 3) * STAGE;
#pragma unroll
        for (int ks = 0; ks < 2; ks++) {
            uint32_t bfh[NT][2], bfl[NT][2];
#pragma unroll
            for (int nt = 0; nt < NT; nt++) {
                int row = wn + nt * 8 + lr;
                int ch = (ks << 1) + (ls & 1);
                uint32_t off = (uint32_t)(row * 64 + ((ch ^ ((row >> 1) & 3)) << 4));
                LDSM_X2(bfh[nt], cb + 2 * ASZ + off);
                LDSM_X2(bfl[nt], cb + 2 * ASZ + BSZ + off);
            }
            uint32_t afh[4][4];
#pragma unroll
            for (int mt = 0; mt < 4; mt++) {
                int row = wm + mt * 16 + ((ls & 1) << 3) + lr;
                int ch = (ks << 1) + (ls >> 1);
                uint32_t off = (uint32_t)(row * 64 + ((ch ^ ((row >> 1) & 3)) << 4));
                LDSM_X4(afh[mt], cb + off);
            }
#pragma unroll
            for (int mt = 0; mt < 4; mt++)
#pragma unroll
                for (int nt = 0; nt < NT; nt++)
                    MMA16816(acc[mt][nt], afh[mt], bfh[nt]);
#pragma unroll
            for (int mt = 0; mt < 4; mt++)
#pragma unroll
                for (int nt = 0; nt < NT; nt++)
                    MMA16816(acc[mt][nt], afh[mt], bfl[nt]);
            uint32_t afl[4][4];
#pragma unroll
            for (int mt = 0; mt < 4; mt++) {
                int row = wm + mt * 16 + ((ls & 1) << 3) + lr;
                int ch = (ks << 1) + (ls >> 1);
                uint32_t off = (uint32_t)(row * 64 + ((ch ^ ((row >> 1) & 3)) << 4));
                LDSM_X4(afl[mt], cb + ASZ + off);
            }
#pragma unroll
            for (int mt = 0; mt < 4; mt++)
#pragma unroll
                for (int nt = 0; nt < NT; nt++)
                    MMA16816(acc[mt][nt], afl[mt], bfh[nt]);
        }
        __syncthreads();
    }

    // ---- epilogue (inline bias) ----
#pragma unroll
    for (int mt = 0; mt < 4; mt++) {
        const int r0 = m0 + wm + mt * 16 + (lane >> 2);
#pragma unroll
        for (int nt = 0; nt < NT; nt++) {
            const int cloc = wn + nt * 8 + ((lane & 3) << 1);
            if (cloc >= ntile) continue;
            const int col = n0 + cloc;
            float bx, by;
            if (MODE == 0) {
                bx = bq[col]; by = bq[col + 1];
            } else {
                if (col < 1024)       { bx = bq[col];        by = bq[col + 1]; }
                else if (col >= 3072) { bx = br[col - 3072]; by = br[col - 3071]; }
                else                  { bx = 0.f;            by = 0.f; }
            }
            float v00 = acc[mt][nt][0] + bx, v01 = acc[mt][nt][1] + by;
            float v10 = acc[mt][nt][2] + bx, v11 = acc[mt][nt][3] + by;
            if (MODE == 0 || col >= 3072) {
                *reinterpret_cast<float2*>(C + (size_t)r0 * ldc + col) =
                    make_float2(v00, v01);
                *reinterpret_cast<float2*>(C + (size_t)(r0 + 8) * ldc + col) =
                    make_float2(v10, v11);
            } else {
                const float sc = (col < 1024) ? 0.125f : 1.f;
                v00 *= sc; v01 *= sc; v10 *= sc; v11 *= sc;
                float h00 = bfr(v00), h01 = bfr(v01);
                float h10 = bfr(v10), h11 = bfr(v11);
                *reinterpret_cast<uint32_t*>(Oh + (size_t)r0 * 3072 + col) = pk2(h00, h01);
                *reinterpret_cast<uint32_t*>(Ol + (size_t)r0 * 3072 + col) = pk2(v00 - h00, v01 - h01);
                *reinterpret_cast<uint32_t*>(Oh + (size_t)(r0 + 8) * 3072 + col) = pk2(h10, h11);
                *reinterpret_cast<uint32_t*>(Ol + (size_t)(r0 + 8) * 3072 + col) = pk2(v10 - h10, v11 - h11);
            }
        }
    }
}

#define GEMM_SMEM_128 (3 * (2 * 8192 + 2 * 128 * 64))   // 98304
#define GEMM_SMEM_64  (3 * (2 * 8192 + 2 * 64 * 64))    // 73728

// ---------------------------------------------------------------------------
// Tensor-core flash-attention with relative banded bias.
// 128 threads (4 warps); q-tile 64; kv-tile 64; pairing (qb, 31-qb).
// ---------------------------------------------------------------------------
#define oQH 0u
#define oQL 8192u
#define oKH 16384u
#define oKL 24576u
#define oVH 32768u
#define oVL 40960u
#define oE  49152u            // float[64][132] = 33792 B
#define oBH 82944u            // bf16[128][24]  = 6144 B
#define oBL 89088u
#define oRH 95232u            // bf16[64][24]   = 3072 B
#define oRL 98304u
#define ATTN_SMEM 101376

__device__ __forceinline__ void cp_tile64(uint32_t sb, uint32_t off,
                                          const __nv_bfloat16* src, int tid) {
#pragma unroll
    for (int i = 0; i < 4; i++) {
        int idx = tid + i * 128;
        int row = idx >> 3, c = idx & 7;
        uint32_t dst = sb + off + (uint32_t)(row * 128 + ((c ^ (row & 7)) << 4));
        CP_ASYNC16(dst, src + (size_t)row * 3072 + c * 8);
    }
}

__global__ __launch_bounds__(128) void attn_mma(
    const __nv_bfloat16* __restrict__ Ph, const __nv_bfloat16* __restrict__ Pl,
    const float* __restrict__ QKVR, const float* __restrict__ b_nd,
    __nv_bfloat16* __restrict__ AOh, __nv_bfloat16* __restrict__ AOl)
{
    extern __shared__ char smraw[];
    const uint32_t sb = smem_u32(smraw);
    __nv_bfloat16* Bsh = reinterpret_cast<__nv_bfloat16*>(smraw + oBH);
    __nv_bfloat16* Bsl = reinterpret_cast<__nv_bfloat16*>(smraw + oBL);
    __nv_bfloat16* Rsh = reinterpret_cast<__nv_bfloat16*>(smraw + oRH);
    __nv_bfloat16* Rsl = reinterpret_cast<__nv_bfloat16*>(smraw + oRL);
    float* Ef = reinterpret_cast<float*>(smraw + oE);

    const int tid = threadIdx.x, w = tid >> 5, lane = tid & 31;
    const int h = blockIdx.y;

    const int row_l = (w << 4) + (lane >> 2);
    const int row_h = row_l + 8;
    const int col_b = (lane & 3) << 1;

    for (int half = 0; half < 2; half++) {
        const int qb = half ? 31 - (int)blockIdx.x : (int)blockIdx.x;
        const int q0 = qb * 64;
        __syncthreads();

        cp_tile64(sb, oQH, Ph + (size_t)q0 * 3072 + h * 64, tid);
        cp_tile64(sb, oQL, Pl + (size_t)q0 * 3072 + h * 64, tid);
        CP_COMMIT;
        for (int idx = tid; idx < 64 * 16; idx += 128) {
            int row = idx >> 4, n = idx & 15;
            float v = (n < NB)
                ? QKVR[(size_t)(q0 + row) * NQKVR + 3072 + h * NB + n] : 0.f;
            float hh = bfr(v);
            Rsh[row * 24 + n] = __float2bfloat16(hh);
            Rsl[row * 24 + n] = __float2bfloat16(v - hh);
        }

        float o[8][4];
#pragma unroll
        for (int nf = 0; nf < 8; nf++)
#pragma unroll
            for (int v = 0; v < 4; v++) o[nf][v] = 0.f;
        float m_run[2] = {-1e30f, -1e30f}, l_run[2] = {0.f, 0.f};

        for (int kt = 0; kt <= qb; kt++) {
            const int k0 = kt * 64;
            __syncthreads();

            float bv[NB];
            {
                int rel = q0 - k0 - 63 + tid;
                bool ok = (rel >= 0) && (rel < ML);
#pragma unroll
                for (int n = 0; n < NB; n++)
                    bv[n] = ok ? __ldg(b_nd + n * ML + rel) : 0.f;
            }

            cp_tile64(sb, oKH, Ph + (size_t)k0 * 3072 + 1024 + h * 64, tid);
            cp_tile64(sb, oKL, Pl + (size_t)k0 * 3072 + 1024 + h * 64, tid);
            cp_tile64(sb, oVH, Ph + (size_t)k0 * 3072 + 2048 + h * 64, tid);
            cp_tile64(sb, oVL, Pl + (size_t)k0 * 3072 + 2048 + h * 64, tid);
            CP_COMMIT;

#pragma unroll
            for (int n = 0; n < 16; n++) {
                float v = (n < NB) ? bv[n] : 0.f;
                float hh = bfr(v);
                Bsh[tid * 24 + n] = __float2bfloat16(hh);
                Bsl[tid * 24 + n] = __float2bfloat16(v - hh);
            }
            __syncthreads();

            // ---- E = R @ Bslab (64 x 128) ----
            uint32_t aRh[4], aRl[4];
            {
                uint32_t r = (uint32_t)((w << 4) + (lane & 15));
                uint32_t ad = sb + oRH + (r * 24 + ((lane >> 4) << 3)) * 2;
                LDSM_X4(aRh, ad);
                LDSM_X4(aRl, ad + (oRL - oRH));
            }
#pragma unroll
            for (int g = 0; g < 4; g++) {
                uint32_t bh[4][2], bl[4][2];
                float e[4][4];
#pragma unroll
                for (int j = 0; j < 4; j++) {
                    uint32_t r = (uint32_t)((4 * g + j) * 8 + (lane & 7));
                    uint32_t ad = sb + oBH + (r * 24 + (((lane >> 3) & 1) << 3)) * 2;
                    LDSM_X2(bh[j], ad);
                    LDSM_X2(bl[j], ad + (oBL - oBH));
#pragma unroll
                    for (int v = 0; v < 4; v++) e[j][v] = 0.f;
                }
#pragma unroll
                for (int j = 0; j < 4; j++) MMA16816(e[j], aRh, bh[j]);
#pragma unroll
                for (int j = 0; j < 4; j++) MMA16816(e[j], aRh, bl[j]);
#pragma unroll
                for (int j = 0; j < 4; j++) MMA16816(e[j], aRl, bh[j]);
#pragma unroll
                for (int j = 0; j < 4; j++) {
                    int c = (4 * g + j) * 8 + col_b;
                    *reinterpret_cast<float2*>(&Ef[row_l * 132 + c]) =
                        make_float2(e[j][0], e[j][1]);
                    *reinterpret_cast<float2*>(&Ef[row_h * 132 + c]) =
                        make_float2(e[j][2], e[j][3]);
                }
            }
            __syncwarp();

            CP_WAIT(0);
            __syncthreads();

            // ---- S = Q K^T (term-major) ----
            float s[8][4];
#pragma unroll
            for (int nf = 0; nf < 8; nf++)
#pragma unroll
                for (int v = 0; v < 4; v++) s[nf][v] = 0.f;

#pragma unroll
            for (int ks = 0; ks < 4; ks++) {
                uint32_t aqh[4], aql[4];
                uint32_t qr = (uint32_t)((w << 4) + (lane & 15));
                uint32_t chq = (uint32_t)((ks << 1) + (lane >> 4));
                uint32_t qa = sb + oQH + qr * 128 + ((chq ^ (qr & 7)) << 4);
                LDSM_X4(aqh, qa);
                LDSM_X4(aql, qa + 8192);
                uint32_t bh[8][2], bl[8][2];
#pragma unroll
                for (int nf = 0; nf < 8; nf++) {
                    uint32_t kr = (uint32_t)(nf * 8 + (lane & 7));
                    uint32_t chk = (uint32_t)((ks << 1) + ((lane >> 3) & 1));
                    uint32_t ka = sb + oKH + kr * 128 + ((chk ^ (kr & 7)) << 4);
                    LDSM_X2(bh[nf], ka);
                    LDSM_X2(bl[nf], ka + 8192);
                }
#pragma unroll
                for (int nf = 0; nf < 8; nf++) MMA16816(s[nf], aqh, bh[nf]);
#pragma unroll
                for (int nf = 0; nf < 8; nf++) MMA16816(s[nf], aqh, bl[nf]);
#pragma unroll
                for (int nf = 0; nf < 8; nf++) MMA16816(s[nf], aql, bh[nf]);
            }

            const bool diag = (kt == qb);
#pragma unroll
            for (int nf = 0; nf < 8; nf++) {
                int c0 = nf * 8 + col_b;
#pragma unroll
                for (int v = 0; v < 4; v++) {
                    int r = (v < 2) ? row_l : row_h;
                    int c = c0 + (v & 1);
                    s[nf][v] += Ef[r * 132 + (r - c + 63)];
                    if (diag && c > r) s[nf][v] = -1e30f;
                }
            }

            // ---- online softmax ----
            float mt0 = -1e30f, mt1 = -1e30f;
#pragma unroll
            for (int nf = 0; nf < 8; nf++) {
                mt0 = fmaxf(mt0, fmaxf(s[nf][0], s[nf][1]));
                mt1 = fmaxf(mt1, fmaxf(s[nf][2], s[nf][3]));
            }
            mt0 = fmaxf(mt0, __shfl_xor_sync(0xffffffffu, mt0, 1));
            mt0 = fmaxf(mt0, __shfl_xor_sync(0xffffffffu, mt0, 2));
            mt1 = fmaxf(mt1, __shfl_xor_sync(0xffffffffu, mt1, 1));
            mt1 = fmaxf(mt1, __shfl_xor_sync(0xffffffffu, mt1, 2));
            float mn0 = fmaxf(m_run[0], mt0), mn1 = fmaxf(m_run[1], mt1);
            float cr0 = __expf(m_run[0] - mn0), cr1 = __expf(m_run[1] - mn1);
            m_run[0] = mn0; m_run[1] = mn1;

            float sum0 = 0.f, sum1 = 0.f;
            uint32_t phk[8][2], plk[8][2];
#pragma unroll
            for (int nf = 0; nf < 8; nf++) {
                float p0 = __expf(s[nf][0] - mn0);
                float p1 = __expf(s[nf][1] - mn0);
                float p2 = __expf(s[nf][2] - mn1);
                float p3 = __expf(s[nf][3] - mn1);
                sum0 += p0 + p1; sum1 += p2 + p3;
                float h0 = bfr(p0), h1 = bfr(p1), h2 = bfr(p2), h3 = bfr(p3);
                phk[nf][0] = pk2(h0, h1);
                phk[nf][1] = pk2(h2, h3);
                plk[nf][0] = pk2(p0 - h0, p1 - h1);
                plk[nf][1] = pk2(p2 - h2, p3 - h3);
            }
            sum0 += __shfl_xor_sync(0xffffffffu, sum0, 1);
            sum0 += __shfl_xor_sync(0xffffffffu, sum0, 2);
            sum1 += __shfl_xor_sync(0xffffffffu, sum1, 1);
            sum1 += __shfl_xor_sync(0xffffffffu, sum1, 2);
            l_run[0] = l_run[0] * cr0 + sum0;
            l_run[1] = l_run[1] * cr1 + sum1;
#pragma unroll
            for (int nf = 0; nf < 8; nf++) {
                o[nf][0] *= cr0; o[nf][1] *= cr0;
                o[nf][2] *= cr1; o[nf][3] *= cr1;
            }

            // ---- O += P @ V (term-major) ----
#pragma unroll
            for (int ks = 0; ks < 4; ks++) {
                uint32_t aH[4] = {phk[2 * ks][0], phk[2 * ks][1],
                                  phk[2 * ks + 1][0], phk[2 * ks + 1][1]};
                uint32_t aL[4] = {plk[2 * ks][0], plk[2 * ks][1],
                                  plk[2 * ks + 1][0], plk[2 * ks + 1][1]};
                uint32_t vh[4][4], vl[4][4];
#pragma unroll
                for (int nfp = 0; nfp < 4; nfp++) {
                    uint32_t m = (uint32_t)(lane >> 3);
                    uint32_t vr = (uint32_t)(ks * 16 + ((m & 1) << 3) + (lane & 7));
                    uint32_t chv = (uint32_t)((nfp << 1) + (m >> 1));
                    uint32_t va = sb + oVH + vr * 128 + ((chv ^ (vr & 7)) << 4);
                    LDSM_X4T(vh[nfp], va);
                    LDSM_X4T(vl[nfp], va + 8192);
                }
#pragma unroll
                for (int nfp = 0; nfp < 4; nfp++) {
                    MMA16816(o[2 * nfp], aH, vh[nfp]);
                    MMA16816(o[2 * nfp + 1], aH, vh[nfp] + 2);
                }
#pragma unroll
                for (int nfp = 0; nfp < 4; nfp++) {
                    MMA16816(o[2 * nfp], aL, vh[nfp]);
                    MMA16816(o[2 * nfp + 1], aL, vh[nfp] + 2);
                }
#pragma unroll
                for (int nfp = 0; nfp < 4; nfp++) {
                    MMA16816(o[2 * nfp], aH, vl[nfp]);
                    MMA16816(o[2 * nfp + 1], aH, vl[nfp] + 2);
                }
            }
        } // kv loop

        float inv0 = 1.f / l_run[0], inv1 = 1.f / l_run[1];
        const size_t rA = (size_t)(q0 + row_l) * E_DIM + h * 64;
        const size_t rB = (size_t)(q0 + row_h) * E_DIM + h * 64;
#pragma unroll
        for (int nf = 0; nf < 8; nf++) {
            int c0 = nf * 8 + col_b;
            float v0 = o[nf][0] * inv0, v1 = o[nf][1] * inv0;
            float v2 = o[nf][2] * inv1, v3 = o[nf][3] * inv1;
            float h0 = bfr(v0), h1 = bfr(v1), h2 = bfr(v2), h3 = bfr(v3);
            *reinterpret_cast<uint32_t*>(AOh + rA + c0) = pk2(h0, h1);
            *reinterpret_cast<uint32_t*>(AOl + rA + c0) = pk2(v0 - h0, v1 - h1);
            *reinterpret_cast<uint32_t*>(AOh + rB + c0) = pk2(h2, h3);
            *reinterpret_cast<uint32_t*>(AOl + rB + c0) = pk2(v2 - h2, v3 - h3);
        }
    } // half
}

// ---------------------------------------------------------------------------
// Host launcher
// ---------------------------------------------------------------------------
extern "C" void kernel_launch(void* const* d_in, const int* in_sizes, int n_in,
                              void* d_out, int out_size)
{
    const float* X      = (const float*)d_in[0];
    const float* W_q    = (const float*)d_in[1];
    const float* b_q    = (const float*)d_in[2];
    const float* W_k    = (const float*)d_in[3];
    const float* W_v    = (const float*)d_in[4];
    const float* W_proj = (const float*)d_in[5];
    const float* b_proj = (const float*)d_in[6];
    const float* W_r    = (const float*)d_in[7];
    const float* b_r    = (const float*)d_in[8];
    const float* b_nd   = (const float*)d_in[9];

    __nv_bfloat16 *Xh, *Xl, *WTh, *WTl, *Php, *Plp, *AOh, *AOl;
    float *QKVRp;
    cudaGetSymbolAddress((void**)&Xh, g_Xh);
    cudaGetSymbolAddress((void**)&Xl, g_Xl);
    cudaGetSymbolAddress((void**)&WTh, g_WTh);
    cudaGetSymbolAddress((void**)&WTl, g_WTl);
    cudaGetSymbolAddress((void**)&Php, g_Ph);
    cudaGetSymbolAddress((void**)&Plp, g_Pl);
    cudaGetSymbolAddress((void**)&AOh, g_AOh);
    cudaGetSymbolAddress((void**)&AOl, g_AOl);
    cudaGetSymbolAddress((void**)&QKVRp, g_QKVR);

    const int nX = T_SEQ * E_DIM;

    // (1) X split
    fsplit_kernel<<<(nX / 4 + 255) / 256, 256>>>(X, Xh, Xl, nX / 4);
    // (2) all five weights in one launch
    TS5 ts5 = {W_q, W_k, W_v, W_proj, W_r};
    tsplit5_kernel<<<dim3(32, 32, 5), dim3(32, 8)>>>(ts5, WTh, WTl);

    // (3) fused QKV+R projection (BN=128)
    cudaFuncSetAttribute(gemm_mma3<1, 128>,
                         cudaFuncAttributeMaxDynamicSharedMemorySize, GEMM_SMEM_128);
    gemm_mma3<1, 128><<<dim3(26, 16), 256, GEMM_SMEM_128>>>(
        Xh, Xl, WTh, WTl, b_q, b_r, QKVRp, Php, Plp, NQKVR, NQKVR);

    // (4) tensor-core flash attention  <-- profiled launch slot
    cudaFuncSetAttribute(attn_mma, cudaFuncAttributeMaxDynamicSharedMemorySize, ATTN_SMEM);
    attn_mma<<<dim3(16, N_HEADS), 128, ATTN_SMEM>>>(Php, Plp, QKVRp, b_nd, AOh, AOl);

    // (5) output projection (BN=64 -> grid 16x16 = 256 CTAs, 128 SMs busy)
    cudaFuncSetAttribute(gemm_mma3<0, 64>,
                         cudaFuncAttributeMaxDynamicSharedMemorySize, GEMM_SMEM_64);
    gemm_mma3<0, 64><<<dim3(16, 16), 256, GEMM_SMEM_64>>>(
        AOh, AOl,
        WTh + (size_t)3232 * E_DIM, WTl + (size_t)3232 * E_DIM,
        b_proj, nullptr, (float*)d_out, nullptr, nullptr, 1024, 1024);
}

// round 8
// speedup vs baseline: 1.0323x; 1.0323x over previous
#include <cuda_runtime.h>
#include <cuda_bf16.h>
#include <cstdint>

// Problem dims (fixed)
#define T_SEQ 2048
#define E_DIM 1024
#define N_HEADS 16
#define D_HEAD 64
#define NB 10
#define ML 2048
#define NQKVR 3232          // 1024*3 + 160
#define WT_ROWS 4256        // 3232 (QKVR) + 1024 (proj)

// ---------------------------------------------------------------------------
// Scratch (device globals; no runtime allocation allowed)
// ---------------------------------------------------------------------------
__device__ __nv_bfloat16 g_Xh[T_SEQ * E_DIM];
__device__ __nv_bfloat16 g_Xl[T_SEQ * E_DIM];
__device__ __nv_bfloat16 g_WTh[WT_ROWS * E_DIM];
__device__ __nv_bfloat16 g_WTl[WT_ROWS * E_DIM];
__device__ __nv_bfloat16 g_Ph[T_SEQ * 3072];   // QKV hi (Q pre-scaled)
__device__ __nv_bfloat16 g_Pl[T_SEQ * 3072];   // QKV lo
__device__ __nv_bfloat16 g_AOh[T_SEQ * E_DIM];
__device__ __nv_bfloat16 g_AOl[T_SEQ * E_DIM];
__device__ float g_QKVR[T_SEQ * NQKVR];        // only R cols (3072..) used

// ---------------------------------------------------------------------------
// PTX helpers (sm_80-baseline ISA only: mma.sync / ldmatrix / cp.async)
// ---------------------------------------------------------------------------
__device__ __forceinline__ uint32_t smem_u32(const void* p) {
    uint32_t a;
    asm("{ .reg .u64 t; cvta.to.shared.u64 t, %1; cvt.u32.u64 %0, t; }"
        : "=r"(a) : "l"(p));
    return a;
}

#define LDSM_X4(r, a)                                                         \
    asm volatile("ldmatrix.sync.aligned.m8n8.x4.shared.b16 {%0,%1,%2,%3}, [%4];" \
                 : "=r"((r)[0]), "=r"((r)[1]), "=r"((r)[2]), "=r"((r)[3])     \
                 : "r"(a))
#define LDSM_X4T(r, a)                                                        \
    asm volatile("ldmatrix.sync.aligned.m8n8.x4.trans.shared.b16 {%0,%1,%2,%3}, [%4];" \
                 : "=r"((r)[0]), "=r"((r)[1]), "=r"((r)[2]), "=r"((r)[3])     \
                 : "r"(a))
#define LDSM_X2(r, a)                                                         \
    asm volatile("ldmatrix.sync.aligned.m8n8.x2.shared.b16 {%0,%1}, [%2];"    \
                 : "=r"((r)[0]), "=r"((r)[1]) : "r"(a))
#define MMA16816(d, a, b)                                                     \
    asm volatile("mma.sync.aligned.m16n8k16.row.col.f32.bf16.bf16.f32 "       \
                 "{%0,%1,%2,%3},{%4,%5,%6,%7},{%8,%9},{%0,%1,%2,%3};"         \
                 : "+f"((d)[0]), "+f"((d)[1]), "+f"((d)[2]), "+f"((d)[3])     \
                 : "r"((a)[0]), "r"((a)[1]), "r"((a)[2]), "r"((a)[3]),        \
                   "r"((b)[0]), "r"((b)[1]))
#define CP_ASYNC16(dst, src)                                                  \
    asm volatile("cp.async.cg.shared.global [%0], [%1], 16;"                  \
                 :: "r"(dst), "l"(src))
#define CP_COMMIT asm volatile("cp.async.commit_group;" ::: "memory")
#define CP_WAIT(n) asm volatile("cp.async.wait_group %0;" :: "n"(n) : "memory")

__device__ __forceinline__ uint32_t pk2(float a, float b) {
    __nv_bfloat162 t = __floats2bfloat162_rn(a, b);
    return *reinterpret_cast<uint32_t*>(&t);
}
__device__ __forceinline__ float bfr(float x) {
    return __bfloat162float(__float2bfloat16(x));
}

// ---------------------------------------------------------------------------
// Vectorized fp32 -> bf16 hi/lo split
// ---------------------------------------------------------------------------
__global__ void fsplit_kernel(const float* __restrict__ s,
                              __nv_bfloat16* __restrict__ dh,
                              __nv_bfloat16* __restrict__ dl, int n4) {
    int i = blockIdx.x * blockDim.x + threadIdx.x;
    if (i < n4) {
        float4 x = reinterpret_cast<const float4*>(s)[i];
        float h0 = bfr(x.x), h1 = bfr(x.y), h2 = bfr(x.z), h3 = bfr(x.w);
        reinterpret_cast<uint2*>(dh)[i] = make_uint2(pk2(h0, h1), pk2(h2, h3));
        reinterpret_cast<uint2*>(dl)[i] =
            make_uint2(pk2(x.x - h0, x.y - h1), pk2(x.z - h2, x.w - h3));
    }
}

// ---------------------------------------------------------------------------
// Transpose+split: all 5 weights in ONE launch (z selects weight)
// ---------------------------------------------------------------------------
struct TS5 { const float* w0; const float* w1; const float* w2;
             const float* w3; const float* w4; };

__global__ void tsplit5_kernel(TS5 p,
                               __nv_bfloat16* __restrict__ dh,
                               __nv_bfloat16* __restrict__ dl) {
    __shared__ float t[32][33];
    const int z = blockIdx.z;
    const int N = (z == 4) ? 160 : 1024;
    const int n0 = blockIdx.x * 32, k0 = blockIdx.y * 32;
    if (n0 >= N) return;
    const float* W = (&p.w0)[z];
    const int rowoff = (z == 0) ? 0 : (z == 1) ? 1024 : (z == 2) ? 2048
                     : (z == 3) ? 3232 : 3072;
    const int tx = threadIdx.x, ty = threadIdx.y;  // 32 x 8
#pragma unroll
    for (int r = 0; r < 4; r++)
        t[ty + 8 * r][tx] = W[(size_t)(k0 + ty + 8 * r) * N + n0 + tx];
    __syncthreads();
    const int tid = ty * 32 + tx;
#pragma unroll
    for (int rr = 0; rr < 2; rr++) {
        int row = (tid >> 4) + 16 * rr;   // local n
        int c = tid & 15;                 // k pair
        float x0 = t[2 * c][row], x1 = t[2 * c + 1][row];
        float h0 = bfr(x0), h1 = bfr(x1);
        size_t o = (size_t)(rowoff + n0 + row) * E_DIM + k0 + 2 * c;
        *reinterpret_cast<uint32_t*>(dh + o) = pk2(h0, h1);
        *reinterpret_cast<uint32_t*>(dl + o) = pk2(x0 - h0, x1 - h1);
    }
}

// ---------------------------------------------------------------------------
// mma.sync GEMM: C[2048, N] = A[2048,1024] @ BT[N,1024]^T (+ inline bias)
// 3-term bf16 split. CTA tile 128 x BN, BK=32, 8 warps, 3-stage cp.async.
// ---------------------------------------------------------------------------
template <int MODE, int BN>
__global__ __launch_bounds__(256, 2) void gemm_mma3(
    const __nv_bfloat16* __restrict__ Ah, const __nv_bfloat16* __restrict__ Al,
    const __nv_bfloat16* __restrict__ Bh, const __nv_bfloat16* __restrict__ Bl,
    const float* __restrict__ bq, const float* __restrict__ br,
    float* __restrict__ C,
    __nv_bfloat16* __restrict__ Oh, __nv_bfloat16* __restrict__ Ol,
    int N, int ldc)
{
    constexpr int ASZ = 8192;          // 128 rows x 64B
    constexpr int BSZ = BN * 64;       // BN rows x 64B
    constexpr int STAGE = 2 * ASZ + 2 * BSZ;
    constexpr int NT = BN / 32;        // nt count per warp

    extern __shared__ char smraw[];
    const uint32_t sb = smem_u32(smraw);
    const int tid = threadIdx.x, wid = tid >> 5, lane = tid & 31;
    const int m0 = blockIdx.y * 128, n0 = blockIdx.x * BN;
    const int ntile = min(BN, N - n0);

    const int wm = (wid & 1) * 64;
    const int wn = (wid >> 1) * (BN / 4);

    const __nv_bfloat16* baseA_h = Ah + (size_t)m0 * E_DIM;
    const __nv_bfloat16* baseA_l = Al + (size_t)m0 * E_DIM;
    const __nv_bfloat16* baseB_h = Bh + (size_t)n0 * E_DIM;
    const __nv_bfloat16* baseB_l = Bl + (size_t)n0 * E_DIM;

    auto load_tile = [&](int kt, int buf) {
        const uint32_t base = sb + buf * STAGE;
#pragma unroll
        for (int half = 0; half < 2; half++) {
            const __nv_bfloat16* s = (half ? baseA_l : baseA_h) + kt * 32;
            const uint32_t dsta = base + half * ASZ;
#pragma unroll
            for (int i = 0; i < 2; i++) {
                int idx = tid + i * 256;
                int row = idx >> 2, c = idx & 3;
                uint32_t dst = dsta +
                    (uint32_t)(row * 64 + ((c ^ ((row >> 1) & 3)) << 4));
                CP_ASYNC16(dst, s + (size_t)row * E_DIM + c * 8);
            }
        }
#pragma unroll
        for (int half = 0; half < 2; half++) {
            const __nv_bfloat16* s = (half ? baseB_l : baseB_h) + kt * 32;
            const uint32_t dstb = base + 2 * ASZ + half * BSZ;
#pragma unroll
            for (int i = 0; i < BN * 4 / 256; i++) {
                int idx = tid + i * 256;
                int row = idx >> 2, c = idx & 3;
                uint32_t dst = dstb +
                    (uint32_t)(row * 64 + ((c ^ ((row >> 1) & 3)) << 4));
                CP_ASYNC16(dst, s + (size_t)row * E_DIM + c * 8);
            }
        }
    };

    float acc[4][NT][4];
#pragma unroll
    for (int mt = 0; mt < 4; mt++)
#pragma unroll
        for (int nt = 0; nt < NT; nt++)
#pragma unroll
            for (int r = 0; r < 4; r++) acc[mt][nt][r] = 0.f;

    const int lr = lane & 7;
    const int ls = lane >> 3;

    load_tile(0, 0); CP_COMMIT;
    load_tile(1, 1); CP_COMMIT;

    for (int kt = 0; kt < 32; kt++) {
        if (kt < 30) {
            load_tile(kt + 2, (kt + 2) % 3);
            CP_COMMIT;
            CP_WAIT(2);
        } else if (kt == 30) {
            CP_WAIT(1);
        } else {
            CP_WAIT(0);
        }
        __syncthreads();

        const uint32_t cb = sb + (kt % 3) * STAGE;
#pragma unroll
        for (int ks = 0; ks < 2; ks++) {
            uint32_t bfh[NT][2], bfl[NT][2];
#pragma unroll
            for (int nt = 0; nt < NT; nt++) {
                int row = wn + nt * 8 + lr;
                int ch = (ks << 1) + (ls & 1);
                uint32_t off = (uint32_t)(row * 64 + ((ch ^ ((row >> 1) & 3)) << 4));
                LDSM_X2(bfh[nt], cb + 2 * ASZ + off);
                LDSM_X2(bfl[nt], cb + 2 * ASZ + BSZ + off);
            }
            uint32_t afh[4][4];
#pragma unroll
            for (int mt = 0; mt < 4; mt++) {
                int row = wm + mt * 16 + ((ls & 1) << 3) + lr;
                int ch = (ks << 1) + (ls >> 1);
                uint32_t off = (uint32_t)(row * 64 + ((ch ^ ((row >> 1) & 3)) << 4));
                LDSM_X4(afh[mt], cb + off);
            }
#pragma unroll
            for (int mt = 0; mt < 4; mt++)
#pragma unroll
                for (int nt = 0; nt < NT; nt++)
                    MMA16816(acc[mt][nt], afh[mt], bfh[nt]);
#pragma unroll
            for (int mt = 0; mt < 4; mt++)
#pragma unroll
                for (int nt = 0; nt < NT; nt++)
                    MMA16816(acc[mt][nt], afh[mt], bfl[nt]);
            uint32_t afl[4][4];
#pragma unroll
            for (int mt = 0; mt < 4; mt++) {
                int row = wm + mt * 16 + ((ls & 1) << 3) + lr;
                int ch = (ks << 1) + (ls >> 1);
                uint32_t off = (uint32_t)(row * 64 + ((ch ^ ((row >> 1) & 3)) << 4));
                LDSM_X4(afl[mt], cb + ASZ + off);
            }
#pragma unroll
            for (int mt = 0; mt < 4; mt++)
#pragma unroll
                for (int nt = 0; nt < NT; nt++)
                    MMA16816(acc[mt][nt], afl[mt], bfh[nt]);
        }
        __syncthreads();
    }

    // ---- epilogue (inline bias) ----
#pragma unroll
    for (int mt = 0; mt < 4; mt++) {
        const int r0 = m0 + wm + mt * 16 + (lane >> 2);
#pragma unroll
        for (int nt = 0; nt < NT; nt++) {
            const int cloc = wn + nt * 8 + ((lane & 3) << 1);
            if (cloc >= ntile) continue;
            const int col = n0 + cloc;
            float bx, by;
            if (MODE == 0) {
                bx = bq[col]; by = bq[col + 1];
            } else {
                if (col < 1024)       { bx = bq[col];        by = bq[col + 1]; }
                else if (col >= 3072) { bx = br[col - 3072]; by = br[col - 3071]; }
                else                  { bx = 0.f;            by = 0.f; }
            }
            float v00 = acc[mt][nt][0] + bx, v01 = acc[mt][nt][1] + by;
            float v10 = acc[mt][nt][2] + bx, v11 = acc[mt][nt][3] + by;
            if (MODE == 0 || col >= 3072) {
                *reinterpret_cast<float2*>(C + (size_t)r0 * ldc + col) =
                    make_float2(v00, v01);
                *reinterpret_cast<float2*>(C + (size_t)(r0 + 8) * ldc + col) =
                    make_float2(v10, v11);
            } else {
                const float sc = (col < 1024) ? 0.125f : 1.f;
                v00 *= sc; v01 *= sc; v10 *= sc; v11 *= sc;
                float h00 = bfr(v00), h01 = bfr(v01);
                float h10 = bfr(v10), h11 = bfr(v11);
                *reinterpret_cast<uint32_t*>(Oh + (size_t)r0 * 3072 + col) = pk2(h00, h01);
                *reinterpret_cast<uint32_t*>(Ol + (size_t)r0 * 3072 + col) = pk2(v00 - h00, v01 - h01);
                *reinterpret_cast<uint32_t*>(Oh + (size_t)(r0 + 8) * 3072 + col) = pk2(h10, h11);
                *reinterpret_cast<uint32_t*>(Ol + (size_t)(r0 + 8) * 3072 + col) = pk2(v10 - h10, v11 - h11);
            }
        }
    }
}

#define GEMM_SMEM_128 (3 * (2 * 8192 + 2 * 128 * 64))   // 98304
#define GEMM_SMEM_64  (3 * (2 * 8192 + 2 * 64 * 64))    // 73728

// ---------------------------------------------------------------------------
// Tensor-core flash-attention with relative banded bias.
// 128 threads (4 warps); q-tile 64; kv-tile 64; pairing (qb, 31-qb).
// R8: Q/R fragments hoisted to registers; K via paired LDSM_X4; vector B-slab.
// ---------------------------------------------------------------------------
#define oQH 0u
#define oQL 8192u
#define oKH 16384u
#define oKL 24576u
#define oVH 32768u
#define oVL 40960u
#define oE  49152u            // float[64][132] = 33792 B
#define oBH 82944u            // bf16[128][24]  = 6144 B
#define oBL 89088u
#define oRH 95232u            // bf16[64][24]   = 3072 B
#define oRL 98304u
#define ATTN_SMEM 101376

__device__ __forceinline__ void cp_tile64(uint32_t sb, uint32_t off,
                                          const __nv_bfloat16* src, int tid) {
#pragma unroll
    for (int i = 0; i < 4; i++) {
        int idx = tid + i * 128;
        int row = idx >> 3, c = idx & 7;
        uint32_t dst = sb + off + (uint32_t)(row * 128 + ((c ^ (row & 7)) << 4));
        CP_ASYNC16(dst, src + (size_t)row * 3072 + c * 8);
    }
}

__global__ __launch_bounds__(128) void attn_mma(
    const __nv_bfloat16* __restrict__ Ph, const __nv_bfloat16* __restrict__ Pl,
    const float* __restrict__ QKVR, const float* __restrict__ b_nd,
    __nv_bfloat16* __restrict__ AOh, __nv_bfloat16* __restrict__ AOl)
{
    extern __shared__ char smraw[];
    const uint32_t sb = smem_u32(smraw);
    __nv_bfloat16* Bsh = reinterpret_cast<__nv_bfloat16*>(smraw + oBH);
    __nv_bfloat16* Bsl = reinterpret_cast<__nv_bfloat16*>(smraw + oBL);
    __nv_bfloat16* Rsh = reinterpret_cast<__nv_bfloat16*>(smraw + oRH);
    __nv_bfloat16* Rsl = reinterpret_cast<__nv_bfloat16*>(smraw + oRL);
    float* Ef = reinterpret_cast<float*>(smraw + oE);

    const int tid = threadIdx.x, w = tid >> 5, lane = tid & 31;
    const int h = blockIdx.y;

    const int row_l = (w << 4) + (lane >> 2);
    const int row_h = row_l + 8;
    const int col_b = (lane & 3) << 1;

    for (int half = 0; half < 2; half++) {
        const int qb = half ? 31 - (int)blockIdx.x : (int)blockIdx.x;
        const int q0 = qb * 64;
        __syncthreads();  // previous half's smem consumers done

        // ---- async Q tile (hi/lo); R fragment (padded to k=16) ----
        cp_tile64(sb, oQH, Ph + (size_t)q0 * 3072 + h * 64, tid);
        cp_tile64(sb, oQL, Pl + (size_t)q0 * 3072 + h * 64, tid);
        CP_COMMIT;
        for (int idx = tid; idx < 64 * 16; idx += 128) {
            int row = idx >> 4, n = idx & 15;
            float v = (n < NB)
                ? QKVR[(size_t)(q0 + row) * NQKVR + 3072 + h * NB + n] : 0.f;
            float hh = bfr(v);
            Rsh[row * 24 + n] = __float2bfloat16(hh);
            Rsl[row * 24 + n] = __float2bfloat16(v - hh);
        }
        CP_WAIT(0);
        __syncthreads();  // Q landed, R visible

        // ---- hoist Q and R fragments into registers (loop-invariant) ----
        uint32_t qfh[4][4], qfl[4][4];
#pragma unroll
        for (int ks = 0; ks < 4; ks++) {
            uint32_t qr = (uint32_t)((w << 4) + (lane & 15));
            uint32_t chq = (uint32_t)((ks << 1) + (lane >> 4));
            uint32_t qa = sb + oQH + qr * 128 + ((chq ^ (qr & 7)) << 4);
            LDSM_X4(qfh[ks], qa);
            LDSM_X4(qfl[ks], qa + 8192);
        }
        uint32_t aRh[4], aRl[4];
        {
            uint32_t r = (uint32_t)((w << 4) + (lane & 15));
            uint32_t ad = sb + oRH + (r * 24 + ((lane >> 4) << 3)) * 2;
            LDSM_X4(aRh, ad);
            LDSM_X4(aRl, ad + (oRL - oRH));
        }

        float o[8][4];
#pragma unroll
        for (int nf = 0; nf < 8; nf++)
#pragma unroll
            for (int v = 0; v < 4; v++) o[nf][v] = 0.f;
        float m_run[2] = {-1e30f, -1e30f}, l_run[2] = {0.f, 0.f};

        for (int kt = 0; kt <= qb; kt++) {
            const int k0 = kt * 64;
            __syncthreads();  // prev iter compute done (K/V/B/E consumers)

            // prefetch b_nd values (global latency overlapped below)
            float bv[NB];
            {
                int rel = q0 - k0 - 63 + tid;
                bool ok = (rel >= 0) && (rel < ML);
#pragma unroll
                for (int n = 0; n < NB; n++)
                    bv[n] = ok ? __ldg(b_nd + n * ML + rel) : 0.f;
            }

            // async K/V tiles (hi/lo)
            cp_tile64(sb, oKH, Ph + (size_t)k0 * 3072 + 1024 + h * 64, tid);
            cp_tile64(sb, oKL, Pl + (size_t)k0 * 3072 + 1024 + h * 64, tid);
            cp_tile64(sb, oVH, Ph + (size_t)k0 * 3072 + 2048 + h * 64, tid);
            cp_tile64(sb, oVL, Pl + (size_t)k0 * 3072 + 2048 + h * 64, tid);
            CP_COMMIT;

            // B slab split (row tid), vectorized u32 stores
#pragma unroll
            for (int n2 = 0; n2 < 8; n2++) {
                float v0 = (2 * n2 < NB) ? bv[2 * n2] : 0.f;
                float v1 = (2 * n2 + 1 < NB) ? bv[2 * n2 + 1] : 0.f;
                float h0 = bfr(v0), h1 = bfr(v1);
                *reinterpret_cast<uint32_t*>(&Bsh[tid * 24 + 2 * n2]) = pk2(h0, h1);
                *reinterpret_cast<uint32_t*>(&Bsl[tid * 24 + 2 * n2]) =
                    pk2(v0 - h0, v1 - h1);
            }
            __syncthreads();  // B visible

            // ---- E = R @ Bslab (64 x 128) ----
#pragma unroll
            for (int g = 0; g < 4; g++) {
                uint32_t bh[4][2], bl[4][2];
                float e[4][4];
#pragma unroll
                for (int j = 0; j < 4; j++) {
                    uint32_t r = (uint32_t)((4 * g + j) * 8 + (lane & 7));
                    uint32_t ad = sb + oBH + (r * 24 + (((lane >> 3) & 1) << 3)) * 2;
                    LDSM_X2(bh[j], ad);
                    LDSM_X2(bl[j], ad + (oBL - oBH));
#pragma unroll
                    for (int v = 0; v < 4; v++) e[j][v] = 0.f;
                }
#pragma unroll
                for (int j = 0; j < 4; j++) MMA16816(e[j], aRh, bh[j]);
#pragma unroll
                for (int j = 0; j < 4; j++) MMA16816(e[j], aRh, bl[j]);
#pragma unroll
                for (int j = 0; j < 4; j++) MMA16816(e[j], aRl, bh[j]);
#pragma unroll
                for (int j = 0; j < 4; j++) {
                    int c = (4 * g + j) * 8 + col_b;
                    *reinterpret_cast<float2*>(&Ef[row_l * 132 + c]) =
                        make_float2(e[j][0], e[j][1]);
                    *reinterpret_cast<float2*>(&Ef[row_h * 132 + c]) =
                        make_float2(e[j][2], e[j][3]);
                }
            }
            __syncwarp();

            CP_WAIT(0);
            __syncthreads();  // K/V landed

            // ---- S = Q K^T (Q from registers; K via paired X4) ----
            float s[8][4];
#pragma unroll
            for (int nf = 0; nf < 8; nf++)
#pragma unroll
                for (int v = 0; v < 4; v++) s[nf][v] = 0.f;

#pragma unroll
            for (int ks = 0; ks < 4; ks++) {
                uint32_t bh[8][2], bl[8][2];
#pragma unroll
                for (int nfp = 0; nfp < 4; nfp++) {
                    uint32_t t4[4], t4l[4];
                    uint32_t kr = (uint32_t)((nfp * 2 + (lane >> 4)) * 8 + (lane & 7));
                    uint32_t chk = (uint32_t)((ks << 1) + ((lane >> 3) & 1));
                    uint32_t ka = sb + oKH + kr * 128 + ((chk ^ (kr & 7)) << 4);
                    LDSM_X4(t4, ka);
                    LDSM_X4(t4l, ka + 8192);
                    bh[2 * nfp][0] = t4[0];     bh[2 * nfp][1] = t4[1];
                    bh[2 * nfp + 1][0] = t4[2]; bh[2 * nfp + 1][1] = t4[3];
                    bl[2 * nfp][0] = t4l[0];     bl[2 * nfp][1] = t4l[1];
                    bl[2 * nfp + 1][0] = t4l[2]; bl[2 * nfp + 1][1] = t4l[3];
                }
#pragma unroll
                for (int nf = 0; nf < 8; nf++) MMA16816(s[nf], qfh[ks], bh[nf]);
#pragma unroll
                for (int nf = 0; nf < 8; nf++) MMA16816(s[nf], qfh[ks], bl[nf]);
#pragma unroll
                for (int nf = 0; nf < 8; nf++) MMA16816(s[nf], qfl[ks], bh[nf]);
            }

            // ---- gathered bias + causal mask ----
            const bool diag = (kt == qb);
#pragma unroll
            for (int nf = 0; nf < 8; nf++) {
                int c0 = nf * 8 + col_b;
#pragma unroll
                for (int v = 0; v < 4; v++) {
                    int r = (v < 2) ? row_l : row_h;
                    int c = c0 + (v & 1);
                    s[nf][v] += Ef[r * 132 + (r - c + 63)];
                    if (diag && c > r) s[nf][v] = -1e30f;
                }
            }

            // ---- online softmax ----
            float mt0 = -1e30f, mt1 = -1e30f;
#pragma unroll
            for (int nf = 0; nf < 8; nf++) {
                mt0 = fmaxf(mt0, fmaxf(s[nf][0], s[nf][1]));
                mt1 = fmaxf(mt1, fmaxf(s[nf][2], s[nf][3]));
            }
            mt0 = fmaxf(mt0, __shfl_xor_sync(0xffffffffu, mt0, 1));
            mt0 = fmaxf(mt0, __shfl_xor_sync(0xffffffffu, mt0, 2));
            mt1 = fmaxf(mt1, __shfl_xor_sync(0xffffffffu, mt1, 1));
            mt1 = fmaxf(mt1, __shfl_xor_sync(0xffffffffu, mt1, 2));
            float mn0 = fmaxf(m_run[0], mt0), mn1 = fmaxf(m_run[1], mt1);
            float cr0 = __expf(m_run[0] - mn0), cr1 = __expf(m_run[1] - mn1);
            m_run[0] = mn0; m_run[1] = mn1;

            float sum0 = 0.f, sum1 = 0.f;
            uint32_t phk[8][2], plk[8][2];
#pragma unroll
            for (int nf = 0; nf < 8; nf++) {
                float p0 = __expf(s[nf][0] - mn0);
                float p1 = __expf(s[nf][1] - mn0);
                float p2 = __expf(s[nf][2] - mn1);
                float p3 = __expf(s[nf][3] - mn1);
                sum0 += p0 + p1; sum1 += p2 + p3;
                float h0 = bfr(p0), h1 = bfr(p1), h2 = bfr(p2), h3 = bfr(p3);
                phk[nf][0] = pk2(h0, h1);
                phk[nf][1] = pk2(h2, h3);
                plk[nf][0] = pk2(p0 - h0, p1 - h1);
                plk[nf][1] = pk2(p2 - h2, p3 - h3);
            }
            sum0 += __shfl_xor_sync(0xffffffffu, sum0, 1);
            sum0 += __shfl_xor_sync(0xffffffffu, sum0, 2);
            sum1 += __shfl_xor_sync(0xffffffffu, sum1, 1);
            sum1 += __shfl_xor_sync(0xffffffffu, sum1, 2);
            l_run[0] = l_run[0] * cr0 + sum0;
            l_run[1] = l_run[1] * cr1 + sum1;
#pragma unroll
            for (int nf = 0; nf < 8; nf++) {
                o[nf][0] *= cr0; o[nf][1] *= cr0;
                o[nf][2] *= cr1; o[nf][3] *= cr1;
            }

            // ---- O += P @ V (term-major) ----
#pragma unroll
            for (int ks = 0; ks < 4; ks++) {
                uint32_t aH[4] = {phk[2 * ks][0], phk[2 * ks][1],
                                  phk[2 * ks + 1][0], phk[2 * ks + 1][1]};
                uint32_t aL[4] = {plk[2 * ks][0], plk[2 * ks][1],
                                  plk[2 * ks + 1][0], plk[2 * ks + 1][1]};
                uint32_t vh[4][4], vl[4][4];
#pragma unroll
                for (int nfp = 0; nfp < 4; nfp++) {
                    uint32_t m = (uint32_t)(lane >> 3);
                    uint32_t vr = (uint32_t)(ks * 16 + ((m & 1) << 3) + (lane & 7));
                    uint32_t chv = (uint32_t)((nfp << 1) + (m >> 1));
                    uint32_t va = sb + oVH + vr * 128 + ((chv ^ (vr & 7)) << 4);
                    LDSM_X4T(vh[nfp], va);
                    LDSM_X4T(vl[nfp], va + 8192);
                }
#pragma unroll
                for (int nfp = 0; nfp < 4; nfp++) {
                    MMA16816(o[2 * nfp], aH, vh[nfp]);
                    MMA16816(o[2 * nfp + 1], aH, vh[nfp] + 2);
                }
#pragma unroll
                for (int nfp = 0; nfp < 4; nfp++) {
                    MMA16816(o[2 * nfp], aL, vh[nfp]);
                    MMA16816(o[2 * nfp + 1], aL, vh[nfp] + 2);
                }
#pragma unroll
                for (int nfp = 0; nfp < 4; nfp++) {
                    MMA16816(o[2 * nfp], aH, vl[nfp]);
                    MMA16816(o[2 * nfp + 1], aH, vl[nfp] + 2);
                }
            }
        } // kv loop

        float inv0 = 1.f / l_run[0], inv1 = 1.f / l_run[1];
        const size_t rA = (size_t)(q0 + row_l) * E_DIM + h * 64;
        const size_t rB = (size_t)(q0 + row_h) * E_DIM + h * 64;
#pragma unroll
        for (int nf = 0; nf < 8; nf++) {
            int c0 = nf * 8 + col_b;
            float v0 = o[nf][0] * inv0, v1 = o[nf][1] * inv0;
            float v2 = o[nf][2] * inv1, v3 = o[nf][3] * inv1;
            float h0 = bfr(v0), h1 = bfr(v1), h2 = bfr(v2), h3 = bfr(v3);
            *reinterpret_cast<uint32_t*>(AOh + rA + c0) = pk2(h0, h1);
            *reinterpret_cast<uint32_t*>(AOl + rA + c0) = pk2(v0 - h0, v1 - h1);
            *reinterpret_cast<uint32_t*>(AOh + rB + c0) = pk2(h2, h3);
            *reinterpret_cast<uint32_t*>(AOl + rB + c0) = pk2(v2 - h2, v3 - h3);
        }
    } // half
}

// ---------------------------------------------------------------------------
// Host launcher
// ---------------------------------------------------------------------------
extern "C" void kernel_launch(void* const* d_in, const int* in_sizes, int n_in,
                              void* d_out, int out_size)
{
    const float* X      = (const float*)d_in[0];
    const float* W_q    = (const float*)d_in[1];
    const float* b_q    = (const float*)d_in[2];
    const float* W_k    = (const float*)d_in[3];
    const float* W_v    = (const float*)d_in[4];
    const float* W_proj = (const float*)d_in[5];
    const float* b_proj = (const float*)d_in[6];
    const float* W_r    = (const float*)d_in[7];
    const float* b_r    = (const float*)d_in[8];
    const float* b_nd   = (const float*)d_in[9];

    __nv_bfloat16 *Xh, *Xl, *WTh, *WTl, *Php, *Plp, *AOh, *AOl;
    float *QKVRp;
    cudaGetSymbolAddress((void**)&Xh, g_Xh);
    cudaGetSymbolAddress((void**)&Xl, g_Xl);
    cudaGetSymbolAddress((void**)&WTh, g_WTh);
    cudaGetSymbolAddress((void**)&WTl, g_WTl);
    cudaGetSymbolAddress((void**)&Php, g_Ph);
    cudaGetSymbolAddress((void**)&Plp, g_Pl);
    cudaGetSymbolAddress((void**)&AOh, g_AOh);
    cudaGetSymbolAddress((void**)&AOl, g_AOl);
    cudaGetSymbolAddress((void**)&QKVRp, g_QKVR);

    const int nX = T_SEQ * E_DIM;

    // (1) X split
    fsplit_kernel<<<(nX / 4 + 255) / 256, 256>>>(X, Xh, Xl, nX / 4);
    // (2) all five weights in one launch
    TS5 ts5 = {W_q, W_k, W_v, W_proj, W_r};
    tsplit5_kernel<<<dim3(32, 32, 5), dim3(32, 8)>>>(ts5, WTh, WTl);

    // (3) fused QKV+R projection (BN=128)
    cudaFuncSetAttribute(gemm_mma3<1, 128>,
                         cudaFuncAttributeMaxDynamicSharedMemorySize, GEMM_SMEM_128);
    gemm_mma3<1, 128><<<dim3(26, 16), 256, GEMM_SMEM_128>>>(
        Xh, Xl, WTh, WTl, b_q, b_r, QKVRp, Php, Plp, NQKVR, NQKVR);

    // (4) tensor-core flash attention  <-- profiled launch slot
    cudaFuncSetAttribute(attn_mma, cudaFuncAttributeMaxDynamicSharedMemorySize, ATTN_SMEM);
    attn_mma<<<dim3(16, N_HEADS), 128, ATTN_SMEM>>>(Php, Plp, QKVRp, b_nd, AOh, AOl);

    // (5) output projection (BN=64)
    cudaFuncSetAttribute(gemm_mma3<0, 64>,
                         cudaFuncAttributeMaxDynamicSharedMemorySize, GEMM_SMEM_64);
    gemm_mma3<0, 64><<<dim3(16, 16), 256, GEMM_SMEM_64>>>(
        AOh, AOl,
        WTh + (size_t)3232 * E_DIM, WTl + (size_t)3232 * E_DIM,
        b_proj, nullptr, (float*)d_out, nullptr, nullptr, 1024, 1024);
}